// round 8
// baseline (speedup 1.0000x reference)
#include <cuda_runtime.h>
#include <cstdint>

// ---------------------------------------------------------------------------
// ActivityDecaySNN: 3-layer LIF SNN forward. T=50, B=512, 784->800->800->10.
// BITWISE CONSTRAINT: currents must reproduce the reference's ascending-k fp32
// FMA chain per element. GEMM1: f32x2-packed SIMT SGEMM (pairs along m; each
// half of fma.rn.f32x2 is an independent fma.rn.f32 -> bitwise identical).
// GEMM2: binary-spike input -> sparse ascending gather (bitwise-exact skips).
// d_out: out[512*10] | s1r[50*512*800] | s2r[50*512*800] | s3r[50*512*10]
// ---------------------------------------------------------------------------

#define T_STEPS 50
#define BATCH   512
#define DIN     784
#define HID     800
#define NOUT    10
#define M_ROWS  (T_STEPS * BATCH)   // 25600
#define SBK     80                  // GEMM2 k-rows per tile
#define NTILES  10                  // 800 / 80

__device__ float  g_c1[(size_t)M_ROWS * HID];
__device__ float  g_c2[(size_t)M_ROWS * HID];
__device__ float  g_c3[(size_t)M_ROWS * NOUT];
__device__ float  g_w2t[(size_t)HID * HID];
__device__ uint8_t g_klist[(size_t)M_ROWS * HID];
__device__ int    g_kcount[M_ROWS * NTILES];

typedef unsigned long long ull;

// ============================ asm helpers ==================================
__device__ __forceinline__ void fma2(ull& d, ull a, ull b) {
    asm("fma.rn.f32x2 %0, %1, %2, %0;" : "+l"(d) : "l"(a), "l"(b));
}
__device__ __forceinline__ void lds_pair2(ull& a, ull& b, uint32_t addr) {
    asm volatile("ld.shared.v2.u64 {%0,%1}, [%2];" : "=l"(a), "=l"(b) : "r"(addr));
}
__device__ __forceinline__ void sts64d(uint32_t addr, float v) {
    asm volatile("st.shared.v2.f32 [%0], {%1,%2};" :: "r"(addr), "f"(v), "f"(v));
}
__device__ __forceinline__ void sts32(uint32_t addr, float v) {
    asm volatile("st.shared.f32 [%0], %1;" :: "r"(addr), "f"(v));
}
__device__ __forceinline__ float lo32(ull v) { return __uint_as_float((uint32_t)v); }
__device__ __forceinline__ float hi32(ull v) { return __uint_as_float((uint32_t)(v >> 32)); }

// ===========================================================================
// GEMM1 with packed f32x2 FMA, pairs along m.
//   C[M,N] = A[M,K] @ W[N,K]^T + bias[N], K=784 (49 BK=16 tiles).
// BM=BN=128, 256 threads. Thread microtile 8m x 8n = 4 m-pairs x 8 n accs.
// A smem: scalar [kk][128m] rows (512B) -> LDS.128 yields 2 ready m-pairs.
// W smem: duplicated {w,w}, chunked so reads are 16 lanes x 16B contiguous:
//   addr(kk,n) = kk*1040 + chunk(n)*256 + (nj>>2)*16 + (nj&1)*8,
//   chunk(n) = (n>=64)*2 + ((n&3)>>1), nj = n&63.  (row pad 16B vs 1024)
// ===========================================================================
#define G1_BK   16
#define G1_AROW 512
#define G1_WROW 1040
#define G1_ABUF (G1_BK * G1_AROW)    // 8192
#define G1_WBUF (G1_BK * G1_WROW)    // 16640
#define G1_SMEM (2 * G1_ABUF + 2 * G1_WBUF)  // 49664

__global__ __launch_bounds__(256, 2)
void gemm1_fma2(const float* __restrict__ A, const float* __restrict__ W,
                const float* __restrict__ bias, float* __restrict__ C,
                int M, int N, int K)
{
    extern __shared__ char smraw[];
    const uint32_t smb = (uint32_t)__cvta_generic_to_shared(smraw);
    const uint32_t aB  = smb;
    const uint32_t wB  = smb + 2 * G1_ABUF;

    const int tid = threadIdx.x;
    const int tx  = tid & 15;
    const int ty  = tid >> 4;
    const int m0  = blockIdx.y * 128;
    const int n0  = blockIdx.x * 128;

    const int ldCol = (tid & 3) * 4;   // k base within tile
    const int ldRow = tid >> 2;        // 0..63

    // per-pass duplicated-W smem offsets (pass p: n = ldRow + p*64)
    uint32_t woff[2];
    #pragma unroll
    for (int p = 0; p < 2; ++p)
        woff[p] = (uint32_t)(((p * 2 + ((ldRow & 3) >> 1)) << 8) +
                             ((ldRow >> 2) << 4) + ((ldRow & 1) << 3));

    ull acc[4][8];
    #pragma unroll
    for (int i = 0; i < 4; ++i)
        #pragma unroll
        for (int j = 0; j < 8; ++j) acc[i][j] = 0ull;

    const int numTiles = K / G1_BK;    // 49
    const float4 z4 = make_float4(0.f, 0.f, 0.f, 0.f);

    // ---- prologue: stage tile 0 into buffer 0 (both passes) ----
    #pragma unroll
    for (int p = 0; p < 2; ++p) {
        const int r  = ldRow + p * 64;
        const float4 av = *reinterpret_cast<const float4*>(A + (size_t)(m0 + r) * K + ldCol);
        const int wn = n0 + r;
        const float4 wv = (wn < N)
            ? *reinterpret_cast<const float4*>(W + (size_t)wn * K + ldCol) : z4;
        #pragma unroll
        for (int q = 0; q < 4; ++q) {
            sts32(aB + (uint32_t)((ldCol + q) * G1_AROW + r * 4), (&av.x)[q]);
            sts64d(wB + (uint32_t)((ldCol + q) * G1_WROW) + woff[p], (&wv.x)[q]);
        }
    }
    __syncthreads();

    for (int t = 0; t < numTiles; ++t) {
        const int  buf     = t & 1;
        const int  nb      = buf ^ 1;
        const bool hasNext = (t + 1 < numTiles);
        const int  kn      = (t + 1) * G1_BK;

        const uint32_t ab  = aB + buf * G1_ABUF;
        const uint32_t wb  = wB + buf * G1_WBUF;
        const uint32_t abn = aB + nb * G1_ABUF;
        const uint32_t wbn = wB + nb * G1_WBUF;

        float4 pa, pw;

        // -- prefetch pass 0 --
        if (hasNext) {
            const int r = ldRow;
            pa = *reinterpret_cast<const float4*>(A + (size_t)(m0 + r) * K + kn + ldCol);
            const int wn = n0 + r;
            pw = (wn < N)
                ? *reinterpret_cast<const float4*>(W + (size_t)wn * K + kn + ldCol) : z4;
        }

        // -- compute kk 0..7 --
        #pragma unroll
        for (int kk = 0; kk < 8; ++kk) {
            ull ap[4], wd[8];
            const uint32_t aadr = ab + kk * G1_AROW + ty * 32;
            lds_pair2(ap[0], ap[1], aadr);
            lds_pair2(ap[2], ap[3], aadr + 16);
            const uint32_t wadr = wb + kk * G1_WROW + tx * 16;
            lds_pair2(wd[0], wd[1], wadr);
            lds_pair2(wd[2], wd[3], wadr + 256);
            lds_pair2(wd[4], wd[5], wadr + 512);
            lds_pair2(wd[6], wd[7], wadr + 768);
            #pragma unroll
            for (int i = 0; i < 4; ++i)
                #pragma unroll
                for (int j = 0; j < 8; ++j)
                    fma2(acc[i][j], ap[i], wd[j]);
        }

        // -- store pass 0, prefetch pass 1 --
        if (hasNext) {
            #pragma unroll
            for (int q = 0; q < 4; ++q) {
                sts32(abn + (uint32_t)((ldCol + q) * G1_AROW + ldRow * 4), (&pa.x)[q]);
                sts64d(wbn + (uint32_t)((ldCol + q) * G1_WROW) + woff[0], (&pw.x)[q]);
            }
            const int r = ldRow + 64;
            pa = *reinterpret_cast<const float4*>(A + (size_t)(m0 + r) * K + kn + ldCol);
            const int wn = n0 + r;
            pw = (wn < N)
                ? *reinterpret_cast<const float4*>(W + (size_t)wn * K + kn + ldCol) : z4;
        }

        // -- compute kk 8..15 --
        #pragma unroll
        for (int kk = 8; kk < 16; ++kk) {
            ull ap[4], wd[8];
            const uint32_t aadr = ab + kk * G1_AROW + ty * 32;
            lds_pair2(ap[0], ap[1], aadr);
            lds_pair2(ap[2], ap[3], aadr + 16);
            const uint32_t wadr = wb + kk * G1_WROW + tx * 16;
            lds_pair2(wd[0], wd[1], wadr);
            lds_pair2(wd[2], wd[3], wadr + 256);
            lds_pair2(wd[4], wd[5], wadr + 512);
            lds_pair2(wd[6], wd[7], wadr + 768);
            #pragma unroll
            for (int i = 0; i < 4; ++i)
                #pragma unroll
                for (int j = 0; j < 8; ++j)
                    fma2(acc[i][j], ap[i], wd[j]);
        }

        // -- store pass 1, publish buffer --
        if (hasNext) {
            const int r = ldRow + 64;
            #pragma unroll
            for (int q = 0; q < 4; ++q) {
                sts32(abn + (uint32_t)((ldCol + q) * G1_AROW + r * 4), (&pa.x)[q]);
                sts64d(wbn + (uint32_t)((ldCol + q) * G1_WROW) + woff[1], (&pw.x)[q]);
            }
            __syncthreads();
        }
    }

    // ---- epilogue: unpack m-pairs, add bias, store ----
    #pragma unroll
    for (int p = 0; p < 4; ++p) {
        const int mA = m0 + ty * 8 + 2 * p;
        const int mB = mA + 1;
        {
            const int n = n0 + tx * 4;
            if (n < N) {
                float4 va, vb;
                va.x = lo32(acc[p][0]) + bias[n + 0];
                va.y = lo32(acc[p][1]) + bias[n + 1];
                va.z = lo32(acc[p][2]) + bias[n + 2];
                va.w = lo32(acc[p][3]) + bias[n + 3];
                vb.x = hi32(acc[p][0]) + bias[n + 0];
                vb.y = hi32(acc[p][1]) + bias[n + 1];
                vb.z = hi32(acc[p][2]) + bias[n + 2];
                vb.w = hi32(acc[p][3]) + bias[n + 3];
                *reinterpret_cast<float4*>(C + (size_t)mA * N + n) = va;
                *reinterpret_cast<float4*>(C + (size_t)mB * N + n) = vb;
            }
        }
        {
            const int n = n0 + 64 + tx * 4;
            if (n < N) {
                float4 va, vb;
                va.x = lo32(acc[p][4]) + bias[n + 0];
                va.y = lo32(acc[p][5]) + bias[n + 1];
                va.z = lo32(acc[p][6]) + bias[n + 2];
                va.w = lo32(acc[p][7]) + bias[n + 3];
                vb.x = hi32(acc[p][4]) + bias[n + 0];
                vb.y = hi32(acc[p][5]) + bias[n + 1];
                vb.z = hi32(acc[p][6]) + bias[n + 2];
                vb.w = hi32(acc[p][7]) + bias[n + 3];
                *reinterpret_cast<float4*>(C + (size_t)mA * N + n) = va;
                *reinterpret_cast<float4*>(C + (size_t)mB * N + n) = vb;
            }
        }
    }
}

// ===========================================================================
// W2 transpose (unchanged from R7).
// ===========================================================================
__global__ void transpose_w2(const float* __restrict__ W, float* __restrict__ WT)
{
    __shared__ float t[32][33];
    const int bx = blockIdx.x * 32, by = blockIdx.y * 32;
    #pragma unroll
    for (int r = 0; r < 4; ++r)
        t[threadIdx.y + r * 8][threadIdx.x] =
            W[(size_t)(by + threadIdx.y + r * 8) * HID + bx + threadIdx.x];
    __syncthreads();
    #pragma unroll
    for (int r = 0; r < 4; ++r)
        WT[(size_t)(bx + threadIdx.y + r * 8) * HID + by + threadIdx.x] =
            t[threadIdx.x][threadIdx.y + r * 8];
}

// ===========================================================================
// Segmented padded u8 k-lists (unchanged from R7).
// ===========================================================================
__global__ __launch_bounds__(256)
void build_klist(const float* __restrict__ spk,
                 uint8_t* __restrict__ klist, int* __restrict__ kcount)
{
    const int m    = blockIdx.x * 8 + (threadIdx.x >> 5);
    const int lane = threadIdx.x & 31;
    const float* row = spk + (size_t)m * HID;
    uint8_t* kl = klist + (size_t)m * HID;

    #pragma unroll
    for (int t = 0; t < NTILES; ++t) {
        int base = 0;
        #pragma unroll
        for (int j = 0; j < SBK; j += 32) {
            const int kloc  = j + lane;
            const bool act  = (kloc < SBK) && (row[t * SBK + kloc] > 0.5f);
            const unsigned mask = __ballot_sync(0xffffffffu, act);
            if (act)
                kl[t * SBK + base + __popc(mask & ((1u << lane) - 1u))] = (uint8_t)kloc;
            base += __popc(mask);
        }
        const int padUp = min((base + 7) & ~7, SBK);
        const int idx   = base + lane;
        if (idx < padUp) kl[t * SBK + idx] = (uint8_t)SBK;
        if (lane == 0) kcount[m * NTILES + t] = base;
    }
}

// ===========================================================================
// Sparse GEMM2 (unchanged from R7 — at crossbar floor).
// ===========================================================================
__global__ __launch_bounds__(256, 2)
void gemm2_sparse(const uint8_t* __restrict__ klist,
                  const int* __restrict__ kcount,
                  const float* __restrict__ WT,
                  const float* __restrict__ bias, float* __restrict__ C)
{
    __shared__ float wt[(SBK + 1) * 128];

    const int tid   = threadIdx.x;
    const int warp  = tid >> 5;
    const int lane  = tid & 31;
    const int n0    = blockIdx.x * 128;
    const int m0w   = blockIdx.y * 128 + warp * 16;
    const int lane4 = lane * 4;

    if (tid < 32)
        *reinterpret_cast<float4*>(&wt[SBK * 128 + tid * 4]) =
            make_float4(0.f, 0.f, 0.f, 0.f);

    float acc[16][4];
    #pragma unroll
    for (int mi = 0; mi < 16; ++mi)
        #pragma unroll
        for (int j = 0; j < 4; ++j) acc[mi][j] = 0.0f;

#define ADD1(WRD, SH)                                                         \
    {                                                                         \
        const int k_ = ((WRD) >> (SH)) & 0xFF;                                \
        const float4 wv_ = *reinterpret_cast<const float4*>(                  \
            &wt[k_ * 128 + lane4]);                                           \
        acc[mi][0] += wv_.x; acc[mi][1] += wv_.y;                             \
        acc[mi][2] += wv_.z; acc[mi][3] += wv_.w;                             \
    }

    for (int t = 0; t < NTILES; ++t) {
        __syncthreads();
        #pragma unroll
        for (int p = 0; p < SBK * 32 / 256; ++p) {
            const int i   = tid + p * 256;
            const int row = i >> 5, c4 = i & 31;
            const int gn  = n0 + c4 * 4;
            const float4 v = (gn < HID)
                ? *reinterpret_cast<const float4*>(WT + (size_t)(t * SBK + row) * HID + gn)
                : make_float4(0.f, 0.f, 0.f, 0.f);
            *reinterpret_cast<float4*>(&wt[row * 128 + c4 * 4]) = v;
        }
        __syncthreads();

        #pragma unroll
        for (int mi = 0; mi < 16; ++mi) {
            const int m   = m0w + mi;
            const int cnt = __ldg(kcount + m * NTILES + t);
            const uint2* klp = reinterpret_cast<const uint2*>(
                klist + (size_t)m * HID + t * SBK);
            const int nbatch = (cnt + 7) >> 3;
            for (int b = 0; b < nbatch; ++b) {
                const uint2 kv = __ldg(klp + b);
                ADD1(kv.x, 0)  ADD1(kv.x, 8)  ADD1(kv.x, 16) ADD1(kv.x, 24)
                ADD1(kv.y, 0)  ADD1(kv.y, 8)  ADD1(kv.y, 16) ADD1(kv.y, 24)
            }
        }
    }
#undef ADD1

    const int gn = n0 + lane4;
    if (gn < HID) {
        const float4 b = *reinterpret_cast<const float4*>(bias + gn);
        #pragma unroll
        for (int mi = 0; mi < 16; ++mi) {
            float4 v;
            v.x = acc[mi][0] + b.x;
            v.y = acc[mi][1] + b.y;
            v.z = acc[mi][2] + b.z;
            v.w = acc[mi][3] + b.w;
            *reinterpret_cast<float4*>(C + (size_t)(m0w + mi) * HID + gn) = v;
        }
    }
}

// ===========================================================================
// LIF kernels (unchanged).
// ===========================================================================
__global__ void lif_kernel4(const float4* __restrict__ cur,
                            float4* __restrict__ spk,
                            const float* __restrict__ beta_ptr, int BH4)
{
    const int idx = blockIdx.x * blockDim.x + threadIdx.x;
    if (idx >= BH4) return;
    const float beta = fminf(fmaxf(beta_ptr[0], 0.0f), 1.0f);
    float4 mem = make_float4(0.f, 0.f, 0.f, 0.f);
    float4 rst = make_float4(0.f, 0.f, 0.f, 0.f);
    #pragma unroll
    for (int t = 0; t < T_STEPS; ++t) {
        const float4 c = cur[(size_t)t * BH4 + idx];
        float4 s;
        mem.x = beta * mem.x + c.x - rst.x; s.x = (mem.x - 1.0f > 0.0f) ? 1.0f : 0.0f;
        mem.y = beta * mem.y + c.y - rst.y; s.y = (mem.y - 1.0f > 0.0f) ? 1.0f : 0.0f;
        mem.z = beta * mem.z + c.z - rst.z; s.z = (mem.z - 1.0f > 0.0f) ? 1.0f : 0.0f;
        mem.w = beta * mem.w + c.w - rst.w; s.w = (mem.w - 1.0f > 0.0f) ? 1.0f : 0.0f;
        spk[(size_t)t * BH4 + idx] = s;
        rst = s;
    }
}

__global__ __launch_bounds__(256)
void gemm3_kernel(const float* __restrict__ S2, const float* __restrict__ W3,
                  const float* __restrict__ b3, float* __restrict__ C3, int M)
{
    __shared__ float w3s[NOUT * HID];
    for (int i = threadIdx.x; i < NOUT * HID; i += 256) w3s[i] = W3[i];
    __syncthreads();

    const int warp = threadIdx.x >> 5;
    const int lane = threadIdx.x & 31;
    const int row  = blockIdx.x * 8 + warp;
    if (row >= M) return;

    const float* s = S2 + (size_t)row * HID;
    float sv[HID / 32];
    #pragma unroll
    for (int i = 0; i < HID / 32; ++i) sv[i] = s[lane + i * 32];

    float accv[NOUT];
    #pragma unroll
    for (int o = 0; o < NOUT; ++o) {
        float a = 0.0f;
        #pragma unroll
        for (int i = 0; i < HID / 32; ++i)
            a += sv[i] * w3s[o * HID + lane + i * 32];
        accv[o] = a;
    }
    #pragma unroll
    for (int o = 0; o < NOUT; ++o) {
        float v = accv[o];
        #pragma unroll
        for (int off = 16; off > 0; off >>= 1)
            v += __shfl_down_sync(0xffffffffu, v, off);
        if (lane == 0) C3[(size_t)row * NOUT + o] = v + b3[o];
    }
}

__global__ void lif3_kernel(const float* __restrict__ C3,
                            float* __restrict__ s3r, float* __restrict__ out,
                            const float* __restrict__ beta_ptr)
{
    const int idx = blockIdx.x * blockDim.x + threadIdx.x;
    if (idx >= BATCH * NOUT) return;
    const float beta = fminf(fmaxf(beta_ptr[0], 0.0f), 1.0f);
    float mem = 0.0f, rst = 0.0f, sum = 0.0f;
    #pragma unroll
    for (int t = 0; t < T_STEPS; ++t) {
        const float c = C3[(size_t)t * BATCH * NOUT + idx];
        mem = beta * mem + c - rst;
        const float s = (mem - 1.0f > 0.0f) ? 1.0f : 0.0f;
        s3r[(size_t)t * BATCH * NOUT + idx] = s;
        sum += s;
        rst = s;
    }
    out[idx] = sum;
}

// ===========================================================================
extern "C" void kernel_launch(void* const* d_in, const int* in_sizes, int n_in,
                              void* d_out, int out_size)
{
    const float* x     = (const float*)d_in[0];
    const float* W1    = (const float*)d_in[1];
    const float* b1    = (const float*)d_in[2];
    const float* W2    = (const float*)d_in[3];
    const float* b2    = (const float*)d_in[4];
    const float* W3    = (const float*)d_in[5];
    const float* b3    = (const float*)d_in[6];
    const float* beta1 = (const float*)d_in[7];
    const float* beta2 = (const float*)d_in[8];
    const float* beta3 = (const float*)d_in[9];

    float* out = (float*)d_out;
    float* s1r = out + (size_t)BATCH * NOUT;
    float* s2r = s1r + (size_t)M_ROWS * HID;
    float* s3r = s2r + (size_t)M_ROWS * HID;

    float *c1, *c2, *c3, *w2t;
    uint8_t* klist;
    int* kcount;
    cudaGetSymbolAddress((void**)&c1, g_c1);
    cudaGetSymbolAddress((void**)&c2, g_c2);
    cudaGetSymbolAddress((void**)&c3, g_c3);
    cudaGetSymbolAddress((void**)&w2t, g_w2t);
    cudaGetSymbolAddress((void**)&klist, g_klist);
    cudaGetSymbolAddress((void**)&kcount, g_kcount);

    static bool attr_set = false;
    if (!attr_set) {
        cudaFuncSetAttribute(gemm1_fma2, cudaFuncAttributeMaxDynamicSharedMemorySize, G1_SMEM);
        attr_set = true;
    }

    const int BH  = BATCH * HID;
    const int BH4 = BH / 4;
    const dim3 grid((HID + 127) / 128, M_ROWS / 128);

    // 0) W2 -> W2T
    {
        dim3 tg(HID / 32, HID / 32);
        transpose_w2<<<tg, dim3(32, 8)>>>(W2, w2t);
    }

    // 1) C1 = X @ W1^T + b1  (f32x2 packed SGEMM, K=784)
    gemm1_fma2<<<grid, 256, G1_SMEM>>>(x, W1, b1, c1, M_ROWS, HID, DIN);

    // 2) LIF1 -> s1r
    lif_kernel4<<<(BH4 + 255) / 256, 256>>>((const float4*)c1, (float4*)s1r, beta1, BH4);

    // 3a) segmented padded u8 k-lists from s1r
    build_klist<<<M_ROWS / 8, 256>>>(s1r, klist, kcount);

    // 3b) sparse GEMM2
    {
        dim3 sg((HID + 127) / 128, M_ROWS / 128);
        gemm2_sparse<<<sg, 256>>>(klist, kcount, w2t, b2, c2);
    }

    // 4) LIF2 -> s2r
    lif_kernel4<<<(BH4 + 255) / 256, 256>>>((const float4*)c2, (float4*)s2r, beta2, BH4);

    // 5) C3 = S2 @ W3^T + b3
    gemm3_kernel<<<M_ROWS / 8, 256>>>(s2r, W3, b3, c3, M_ROWS);

    // 6) LIF3 + sum
    lif3_kernel<<<(BATCH * NOUT + 255) / 256, 256>>>(c3, s3r, out, beta3);
}

// round 9
// speedup vs baseline: 1.1721x; 1.1721x over previous
#include <cuda_runtime.h>
#include <cstdint>

// ---------------------------------------------------------------------------
// ActivityDecaySNN: 3-layer LIF SNN forward. T=50, B=512, 784->800->800->10.
// BITWISE CONSTRAINT: currents must reproduce the reference's ascending-k fp32
// FMA chain per element. GEMM1: scalar SIMT SGEMM (at the FFMA issue roofline;
// f32x2 disproven twice - RF banking caps FFMA2 at rt=3). GEMM2: binary-spike
// input -> sparse ascending gather of W2T rows, u8 k-lists in batches of 4
// padded with sentinel k=SBK (zeroed smem row: acc += +0.0 identity).
// d_out: out[512*10] | s1r[50*512*800] | s2r[50*512*800] | s3r[50*512*10]
// ---------------------------------------------------------------------------

#define T_STEPS 50
#define BATCH   512
#define DIN     784
#define HID     800
#define NOUT    10
#define M_ROWS  (T_STEPS * BATCH)   // 25600
#define SBK     100                 // GEMM2 k-rows per tile
#define NTILES  8                   // 800 / 100

__device__ float  g_c1[(size_t)M_ROWS * HID];
__device__ float  g_c2[(size_t)M_ROWS * HID];
__device__ float  g_c3[(size_t)M_ROWS * NOUT];
__device__ float  g_w2t[(size_t)HID * HID];
__device__ uint8_t g_klist[(size_t)M_ROWS * HID];
__device__ int    g_kcount[M_ROWS * NTILES];

// ===========================================================================
// W2 transpose: W2T[k][n] = W2[n][k]. 32x32 tiles.
// ===========================================================================
__global__ void transpose_w2(const float* __restrict__ W, float* __restrict__ WT)
{
    __shared__ float t[32][33];
    const int bx = blockIdx.x * 32, by = blockIdx.y * 32;
    #pragma unroll
    for (int r = 0; r < 4; ++r)
        t[threadIdx.y + r * 8][threadIdx.x] =
            W[(size_t)(by + threadIdx.y + r * 8) * HID + bx + threadIdx.x];
    __syncthreads();
    #pragma unroll
    for (int r = 0; r < 4; ++r)
        WT[(size_t)(bx + threadIdx.y + r * 8) * HID + by + threadIdx.x] =
            t[threadIdx.x][threadIdx.y + r * 8];
}

// ===========================================================================
// Segmented u8 k-lists: local k within each 100-row tile, ascending, padded
// with sentinel SBK to the next multiple of 4. One warp per row m.
// ===========================================================================
__global__ __launch_bounds__(256)
void build_klist(const float* __restrict__ spk,
                 uint8_t* __restrict__ klist, int* __restrict__ kcount)
{
    const int m    = blockIdx.x * 8 + (threadIdx.x >> 5);
    const int lane = threadIdx.x & 31;
    const float* row = spk + (size_t)m * HID;
    uint8_t* kl = klist + (size_t)m * HID;

    #pragma unroll
    for (int t = 0; t < NTILES; ++t) {
        int base = 0;
        #pragma unroll
        for (int j = 0; j < SBK; j += 32) {
            const int kloc  = j + lane;
            const bool act  = (kloc < SBK) && (row[t * SBK + kloc] > 0.5f);
            const unsigned mask = __ballot_sync(0xffffffffu, act);
            if (act)
                kl[t * SBK + base + __popc(mask & ((1u << lane) - 1u))] = (uint8_t)kloc;
            base += __popc(mask);
        }
        // pad to multiple of 4 with sentinel (maps to zeroed smem row)
        const int padUp = min((base + 3) & ~3, SBK);
        const int idx   = base + lane;
        if (idx < padUp) kl[t * SBK + idx] = (uint8_t)SBK;
        if (lane == 0) kcount[m * NTILES + t] = base;
    }
}

// ===========================================================================
// Sparse GEMM2: C2[m,n] = b2[n] + sum_{k active(m), ascending} W2T[k][n]
// Block: 128 m x 128 n; 8 warps, warp owns 16 m-rows (uniform lists -> no
// divergence). W2T staged in 100-row tiles + zero sentinel row (50.5 KB dyn).
// Inner loop: batches of 4 k's (one LDG.32 -> 4 independent LDS.128).
// ===========================================================================
__global__ __launch_bounds__(256, 2)
void gemm2_sparse(const uint8_t* __restrict__ klist,
                  const int* __restrict__ kcount,
                  const float* __restrict__ WT,
                  const float* __restrict__ bias, float* __restrict__ C)
{
    extern __shared__ float wt[];           // (SBK+1) * 128 floats

    const int tid   = threadIdx.x;
    const int warp  = tid >> 5;
    const int lane  = tid & 31;
    const int n0    = blockIdx.x * 128;
    const int m0w   = blockIdx.y * 128 + warp * 16;
    const int lane4 = lane * 4;

    // zero the sentinel row once (never touched by staging)
    if (tid < 32)
        *reinterpret_cast<float4*>(&wt[SBK * 128 + tid * 4]) =
            make_float4(0.f, 0.f, 0.f, 0.f);

    float acc[16][4];
    #pragma unroll
    for (int mi = 0; mi < 16; ++mi)
        #pragma unroll
        for (int j = 0; j < 4; ++j) acc[mi][j] = 0.0f;

#define ADD1(WRD, SH)                                                         \
    {                                                                         \
        const int k_ = ((WRD) >> (SH)) & 0xFF;                                \
        const float4 wv_ = *reinterpret_cast<const float4*>(                  \
            &wt[k_ * 128 + lane4]);                                           \
        acc[mi][0] += wv_.x; acc[mi][1] += wv_.y;                             \
        acc[mi][2] += wv_.z; acc[mi][3] += wv_.w;                             \
    }

    for (int t = 0; t < NTILES; ++t) {
        __syncthreads();   // protect previous tile (and sentinel) before restage
        // ---- stage W2T[t*100 : t*100+100, n0 : n0+128) : 3200 chunks ----
        #pragma unroll
        for (int p = 0; p < 13; ++p) {
            const int i = tid + p * 256;
            if (i < SBK * 32) {
                const int row = i >> 5, c4 = i & 31;
                const int gn  = n0 + c4 * 4;
                const float4 v = (gn < HID)
                    ? *reinterpret_cast<const float4*>(WT + (size_t)(t * SBK + row) * HID + gn)
                    : make_float4(0.f, 0.f, 0.f, 0.f);
                *reinterpret_cast<float4*>(&wt[row * 128 + c4 * 4]) = v;
            }
        }
        __syncthreads();

        #pragma unroll
        for (int mi = 0; mi < 16; ++mi) {
            const int m   = m0w + mi;
            const int cnt = __ldg(kcount + m * NTILES + t);
            const uint32_t* klp = reinterpret_cast<const uint32_t*>(
                klist + (size_t)m * HID + t * SBK);
            const int nbatch = (cnt + 3) >> 2;
            for (int b = 0; b < nbatch; ++b) {
                const uint32_t kv = __ldg(klp + b);
                ADD1(kv, 0)  ADD1(kv, 8)  ADD1(kv, 16) ADD1(kv, 24)
            }
        }
    }
#undef ADD1

    // ---- epilogue: bias + store ----
    const int gn = n0 + lane4;
    if (gn < HID) {
        const float4 b = *reinterpret_cast<const float4*>(bias + gn);
        #pragma unroll
        for (int mi = 0; mi < 16; ++mi) {
            float4 v;
            v.x = acc[mi][0] + b.x;
            v.y = acc[mi][1] + b.y;
            v.z = acc[mi][2] + b.z;
            v.w = acc[mi][3] + b.w;
            *reinterpret_cast<float4*>(C + (size_t)(m0w + mi) * HID + gn) = v;
        }
    }
}

// ===========================================================================
// Dense SIMT SGEMM (NT) for layer 1 — R4/R7 version (bitwise, at FFMA floor).
// ===========================================================================
template<int BK>
__global__ __launch_bounds__(256, 2)
void sgemm_nt(const float* __restrict__ A, const float* __restrict__ W,
              const float* __restrict__ bias, float* __restrict__ C,
              int M, int N, int K)
{
    constexpr int QPR    = BK / 4;
    constexpr int ROWSPP = 256 / QPR;
    constexpr int NQ     = BK / 8;
    constexpr int HQ     = NQ / 2;

    extern __shared__ float sm[];
    float* As = sm;
    float* Ws = sm + 2 * BK * 128;

    const int tid = threadIdx.x;
    const int tx  = tid & 15;
    const int ty  = tid >> 4;
    const int m0  = blockIdx.y * 128;
    const int n0  = blockIdx.x * 128;

    const int ldCol = (tid % QPR) * 4;
    const int ldRow = tid / QPR;

    float acc[8][8];
    #pragma unroll
    for (int i = 0; i < 8; ++i)
        #pragma unroll
        for (int j = 0; j < 8; ++j) acc[i][j] = 0.0f;

    const int numTiles = K / BK;
    const float4 z4 = make_float4(0.f, 0.f, 0.f, 0.f);

    #pragma unroll
    for (int p = 0; p < NQ; ++p) {
        const int r  = ldRow + p * ROWSPP;
        const float4 av = *reinterpret_cast<const float4*>(A + (size_t)(m0 + r) * K + ldCol);
        const int wn = n0 + r;
        const float4 wv = (wn < N)
            ? *reinterpret_cast<const float4*>(W + (size_t)wn * K + ldCol) : z4;
        #pragma unroll
        for (int q = 0; q < 4; ++q) {
            As[(ldCol + q) * 128 + r] = (&av.x)[q];
            Ws[(ldCol + q) * 128 + r] = (&wv.x)[q];
        }
    }
    __syncthreads();

    for (int t = 0; t < numTiles; ++t) {
        const int  buf     = t & 1;
        const int  nb      = buf ^ 1;
        const bool hasNext = (t + 1 < numTiles);
        const int  kn      = (t + 1) * BK;

        float* Ab = As + buf * BK * 128;
        float* Wb = Ws + buf * BK * 128;
        float* An = As + nb * BK * 128;
        float* Wn = Ws + nb * BK * 128;

        float4 pa[HQ], pw[HQ];

        if (hasNext) {
            #pragma unroll
            for (int p = 0; p < HQ; ++p) {
                const int r = ldRow + p * ROWSPP;
                pa[p] = *reinterpret_cast<const float4*>(A + (size_t)(m0 + r) * K + kn + ldCol);
                const int wn = n0 + r;
                pw[p] = (wn < N)
                    ? *reinterpret_cast<const float4*>(W + (size_t)wn * K + kn + ldCol) : z4;
            }
        }
        #pragma unroll
        for (int kk = 0; kk < BK / 2; ++kk) {
            float af[8], wf[8];
            *reinterpret_cast<float4*>(&af[0]) = *reinterpret_cast<const float4*>(Ab + kk * 128 + ty * 8);
            *reinterpret_cast<float4*>(&af[4]) = *reinterpret_cast<const float4*>(Ab + kk * 128 + ty * 8 + 4);
            *reinterpret_cast<float4*>(&wf[0]) = *reinterpret_cast<const float4*>(Wb + kk * 128 + tx * 4);
            *reinterpret_cast<float4*>(&wf[4]) = *reinterpret_cast<const float4*>(Wb + kk * 128 + 64 + tx * 4);
            #pragma unroll
            for (int i = 0; i < 8; ++i)
                #pragma unroll
                for (int j = 0; j < 8; ++j)
                    acc[i][j] += af[i] * wf[j];
        }
        if (hasNext) {
            #pragma unroll
            for (int p = 0; p < HQ; ++p) {
                const int r = ldRow + p * ROWSPP;
                #pragma unroll
                for (int q = 0; q < 4; ++q) {
                    An[(ldCol + q) * 128 + r] = (&pa[p].x)[q];
                    Wn[(ldCol + q) * 128 + r] = (&pw[p].x)[q];
                }
            }
            #pragma unroll
            for (int p = 0; p < HQ; ++p) {
                const int r = ldRow + (HQ + p) * ROWSPP;
                pa[p] = *reinterpret_cast<const float4*>(A + (size_t)(m0 + r) * K + kn + ldCol);
                const int wn = n0 + r;
                pw[p] = (wn < N)
                    ? *reinterpret_cast<const float4*>(W + (size_t)wn * K + kn + ldCol) : z4;
            }
        }
        #pragma unroll
        for (int kk = BK / 2; kk < BK; ++kk) {
            float af[8], wf[8];
            *reinterpret_cast<float4*>(&af[0]) = *reinterpret_cast<const float4*>(Ab + kk * 128 + ty * 8);
            *reinterpret_cast<float4*>(&af[4]) = *reinterpret_cast<const float4*>(Ab + kk * 128 + ty * 8 + 4);
            *reinterpret_cast<float4*>(&wf[0]) = *reinterpret_cast<const float4*>(Wb + kk * 128 + tx * 4);
            *reinterpret_cast<float4*>(&wf[4]) = *reinterpret_cast<const float4*>(Wb + kk * 128 + 64 + tx * 4);
            #pragma unroll
            for (int i = 0; i < 8; ++i)
                #pragma unroll
                for (int j = 0; j < 8; ++j)
                    acc[i][j] += af[i] * wf[j];
        }
        if (hasNext) {
            #pragma unroll
            for (int p = 0; p < HQ; ++p) {
                const int r = ldRow + (HQ + p) * ROWSPP;
                #pragma unroll
                for (int q = 0; q < 4; ++q) {
                    An[(ldCol + q) * 128 + r] = (&pa[p].x)[q];
                    Wn[(ldCol + q) * 128 + r] = (&pw[p].x)[q];
                }
            }
            __syncthreads();
        }
    }

    #pragma unroll
    for (int i = 0; i < 8; ++i) {
        const int m = m0 + ty * 8 + i;
        {
            const int n = n0 + tx * 4;
            if (n < N) {
                float4 v;
                v.x = acc[i][0] + bias[n + 0];
                v.y = acc[i][1] + bias[n + 1];
                v.z = acc[i][2] + bias[n + 2];
                v.w = acc[i][3] + bias[n + 3];
                *reinterpret_cast<float4*>(C + (size_t)m * N + n) = v;
            }
        }
        {
            const int n = n0 + 64 + tx * 4;
            if (n < N) {
                float4 v;
                v.x = acc[i][4] + bias[n + 0];
                v.y = acc[i][5] + bias[n + 1];
                v.z = acc[i][6] + bias[n + 2];
                v.w = acc[i][7] + bias[n + 3];
                *reinterpret_cast<float4*>(C + (size_t)m * N + n) = v;
            }
        }
    }
}

// ===========================================================================
// LIF kernels (unchanged).
// ===========================================================================
__global__ void lif_kernel4(const float4* __restrict__ cur,
                            float4* __restrict__ spk,
                            const float* __restrict__ beta_ptr, int BH4)
{
    const int idx = blockIdx.x * blockDim.x + threadIdx.x;
    if (idx >= BH4) return;
    const float beta = fminf(fmaxf(beta_ptr[0], 0.0f), 1.0f);
    float4 mem = make_float4(0.f, 0.f, 0.f, 0.f);
    float4 rst = make_float4(0.f, 0.f, 0.f, 0.f);
    #pragma unroll
    for (int t = 0; t < T_STEPS; ++t) {
        const float4 c = cur[(size_t)t * BH4 + idx];
        float4 s;
        mem.x = beta * mem.x + c.x - rst.x; s.x = (mem.x - 1.0f > 0.0f) ? 1.0f : 0.0f;
        mem.y = beta * mem.y + c.y - rst.y; s.y = (mem.y - 1.0f > 0.0f) ? 1.0f : 0.0f;
        mem.z = beta * mem.z + c.z - rst.z; s.z = (mem.z - 1.0f > 0.0f) ? 1.0f : 0.0f;
        mem.w = beta * mem.w + c.w - rst.w; s.w = (mem.w - 1.0f > 0.0f) ? 1.0f : 0.0f;
        spk[(size_t)t * BH4 + idx] = s;
        rst = s;
    }
}

__global__ __launch_bounds__(256)
void gemm3_kernel(const float* __restrict__ S2, const float* __restrict__ W3,
                  const float* __restrict__ b3, float* __restrict__ C3, int M)
{
    __shared__ float w3s[NOUT * HID];
    for (int i = threadIdx.x; i < NOUT * HID; i += 256) w3s[i] = W3[i];
    __syncthreads();

    const int warp = threadIdx.x >> 5;
    const int lane = threadIdx.x & 31;
    const int row  = blockIdx.x * 8 + warp;
    if (row >= M) return;

    const float* s = S2 + (size_t)row * HID;
    float sv[HID / 32];
    #pragma unroll
    for (int i = 0; i < HID / 32; ++i) sv[i] = s[lane + i * 32];

    float accv[NOUT];
    #pragma unroll
    for (int o = 0; o < NOUT; ++o) {
        float a = 0.0f;
        #pragma unroll
        for (int i = 0; i < HID / 32; ++i)
            a += sv[i] * w3s[o * HID + lane + i * 32];
        accv[o] = a;
    }
    #pragma unroll
    for (int o = 0; o < NOUT; ++o) {
        float v = accv[o];
        #pragma unroll
        for (int off = 16; off > 0; off >>= 1)
            v += __shfl_down_sync(0xffffffffu, v, off);
        if (lane == 0) C3[(size_t)row * NOUT + o] = v + b3[o];
    }
}

__global__ void lif3_kernel(const float* __restrict__ C3,
                            float* __restrict__ s3r, float* __restrict__ out,
                            const float* __restrict__ beta_ptr)
{
    const int idx = blockIdx.x * blockDim.x + threadIdx.x;
    if (idx >= BATCH * NOUT) return;
    const float beta = fminf(fmaxf(beta_ptr[0], 0.0f), 1.0f);
    float mem = 0.0f, rst = 0.0f, sum = 0.0f;
    #pragma unroll
    for (int t = 0; t < T_STEPS; ++t) {
        const float c = C3[(size_t)t * BATCH * NOUT + idx];
        mem = beta * mem + c - rst;
        const float s = (mem - 1.0f > 0.0f) ? 1.0f : 0.0f;
        s3r[(size_t)t * BATCH * NOUT + idx] = s;
        sum += s;
        rst = s;
    }
    out[idx] = sum;
}

// ===========================================================================
extern "C" void kernel_launch(void* const* d_in, const int* in_sizes, int n_in,
                              void* d_out, int out_size)
{
    const float* x     = (const float*)d_in[0];
    const float* W1    = (const float*)d_in[1];
    const float* b1    = (const float*)d_in[2];
    const float* W2    = (const float*)d_in[3];
    const float* b2    = (const float*)d_in[4];
    const float* W3    = (const float*)d_in[5];
    const float* b3    = (const float*)d_in[6];
    const float* beta1 = (const float*)d_in[7];
    const float* beta2 = (const float*)d_in[8];
    const float* beta3 = (const float*)d_in[9];

    float* out = (float*)d_out;
    float* s1r = out + (size_t)BATCH * NOUT;
    float* s2r = s1r + (size_t)M_ROWS * HID;
    float* s3r = s2r + (size_t)M_ROWS * HID;

    float *c1, *c2, *c3, *w2t;
    uint8_t* klist;
    int* kcount;
    cudaGetSymbolAddress((void**)&c1, g_c1);
    cudaGetSymbolAddress((void**)&c2, g_c2);
    cudaGetSymbolAddress((void**)&c3, g_c3);
    cudaGetSymbolAddress((void**)&w2t, g_w2t);
    cudaGetSymbolAddress((void**)&klist, g_klist);
    cudaGetSymbolAddress((void**)&kcount, g_kcount);

    constexpr int SM16   = 4 * 16 * 128 * 4;            // 32 KB
    constexpr int SMEMG2 = (SBK + 1) * 128 * 4;         // 51712 B
    static bool attr_set = false;
    if (!attr_set) {
        cudaFuncSetAttribute(sgemm_nt<16>, cudaFuncAttributeMaxDynamicSharedMemorySize, SM16);
        cudaFuncSetAttribute(gemm2_sparse, cudaFuncAttributeMaxDynamicSharedMemorySize, SMEMG2);
        attr_set = true;
    }

    const int BH  = BATCH * HID;   // 409600
    const int BH4 = BH / 4;
    const dim3 grid((HID + 127) / 128, M_ROWS / 128);

    // 0) W2 -> W2T
    {
        dim3 tg(HID / 32, HID / 32);
        transpose_w2<<<tg, dim3(32, 8)>>>(W2, w2t);
    }

    // 1) C1 = X @ W1^T + b1   (dense scalar SGEMM, K=784, BK=16)
    sgemm_nt<16><<<grid, 256, SM16>>>(x, W1, b1, c1, M_ROWS, HID, DIN);

    // 2) LIF1 -> s1r
    lif_kernel4<<<(BH4 + 255) / 256, 256>>>((const float4*)c1, (float4*)s1r, beta1, BH4);

    // 3a) segmented padded u8 k-lists from s1r
    build_klist<<<M_ROWS / 8, 256>>>(s1r, klist, kcount);

    // 3b) sparse GEMM2 (batch-4, SBK=100)
    {
        dim3 sg((HID + 127) / 128, M_ROWS / 128);
        gemm2_sparse<<<sg, 256, SMEMG2>>>(klist, kcount, w2t, b2, c2);
    }

    // 4) LIF2 -> s2r
    lif_kernel4<<<(BH4 + 255) / 256, 256>>>((const float4*)c2, (float4*)s2r, beta2, BH4);

    // 5) C3 = S2 @ W3^T + b3
    gemm3_kernel<<<M_ROWS / 8, 256>>>(s2r, W3, b3, c3, M_ROWS);

    // 6) LIF3 + sum
    lif3_kernel<<<(BATCH * NOUT + 255) / 256, 256>>>(c3, s3r, out, beta3);
}